// round 12
// baseline (speedup 1.0000x reference)
#include <cuda_runtime.h>
#include <cuda_fp16.h>
#include <cstdint>
#include <math.h>

#define TOKENS 4096
#define DMODEL 1024
#define SEQ    1024
#define NHEAD  16
#define HDIM   64
#define DFF_   4096

// ---------------- scratch (device globals: allocation-free) ----------------
__device__ float g_h[TOKENS * DMODEL];
__device__ __half g_d16[TOKENS * DMODEL];    // fp16 GEMM delta (Wo/Co/W2 out)
__device__ __half g_a16[TOKENS * DMODEL];
__device__ __half g_s16[TOKENS * DMODEL];
__device__ __half g_ff16[TOKENS * DFF_];     // ff fp16; also qkv fp16
__device__ __half g_ff2[TOKENS * DFF_];      // cq fp16 + ckv fp16
__device__ __half g_w16[16777216];
__device__ int g_tk[4];                      // dynamic work tickets

#define OFF_QKV 0
#define OFF_O   3145728
#define OFF_CQ  4194304
#define OFF_CKV 5242880
#define OFF_CO  7340032
#define OFF_W1  8388608
#define OFF_W2  12582912

// ---------------- helpers ----------------
__device__ __forceinline__ uint32_t smem_u32(const void* p) {
    uint32_t a;
    asm("{ .reg .u64 t; cvta.to.shared.u64 t, %1; cvt.u32.u64 %0, t; }" : "=r"(a) : "l"(p));
    return a;
}
__device__ __forceinline__ void cpa16(uint32_t d, const void* g) {
    asm volatile("cp.async.cg.shared.global [%0], [%1], 16;" :: "r"(d), "l"(g));
}
#define CP_COMMIT() asm volatile("cp.async.commit_group;" ::: "memory")
#define LDSM4(r, a) \
    asm volatile("ldmatrix.sync.aligned.m8n8.x4.shared.b16 {%0,%1,%2,%3}, [%4];" \
        : "=r"((r)[0]), "=r"((r)[1]), "=r"((r)[2]), "=r"((r)[3]) : "r"(a))
#define LDSM4T(r, a) \
    asm volatile("ldmatrix.sync.aligned.m8n8.x4.trans.shared.b16 {%0,%1,%2,%3}, [%4];" \
        : "=r"((r)[0]), "=r"((r)[1]), "=r"((r)[2]), "=r"((r)[3]) : "r"(a))

__device__ __forceinline__ void mma_f16(float* d, const uint32_t* a, const uint32_t* b) {
    asm volatile("mma.sync.aligned.m16n8k16.row.col.f32.f16.f16.f32 "
                 "{%0,%1,%2,%3}, {%4,%5,%6,%7}, {%8,%9}, {%0,%1,%2,%3};"
                 : "+f"(d[0]), "+f"(d[1]), "+f"(d[2]), "+f"(d[3])
                 : "r"(a[0]), "r"(a[1]), "r"(a[2]), "r"(a[3]), "r"(b[0]), "r"(b[1]));
}
__device__ __forceinline__ void mma_h16(uint32_t* d, const uint32_t* a, const uint32_t* b) {
    asm volatile("mma.sync.aligned.m16n8k16.row.col.f16.f16.f16.f16 "
                 "{%0,%1}, {%2,%3,%4,%5}, {%6,%7}, {%0,%1};"
                 : "+r"(d[0]), "+r"(d[1])
                 : "r"(a[0]), "r"(a[1]), "r"(a[2]), "r"(a[3]), "r"(b[0]), "r"(b[1]));
}
__device__ __forceinline__ uint32_t packh2(float a, float b) {
    __half2 t = __float22half2_rn(make_float2(a, b));
    return *(uint32_t*)&t;
}

// ---------------- ticket reset ----------------
__global__ void reset_tk() {
    if (threadIdx.x < 4) g_tk[threadIdx.x] = 0;
}

// ---------------- fp16 single-pass HMMA GEMM ----------------
// OUTMODE: 0 = f32 out; 1 = GELU + fp16 out; 2 = fp16 out (qcols scaled); 3 = fp16 out
template <int ACT, int OUTMODE, int NS, int BN, int ACC16>
__global__ __launch_bounds__(256) void gemm_mma(
    const __half* __restrict__ A, const __half* __restrict__ B,
    const float* __restrict__ bias, float* __restrict__ C,
    __half* __restrict__ Ch, int M, int N, int K, int qcols)
{
    constexpr int WNB = (BN == 256) ? 64 : 32;
    constexpr int NH  = WNB / 16;
    constexpr int B_BYTES = BN * 128;
    constexpr int STG = 16384 + B_BYTES;

    extern __shared__ char smem[];
    uint32_t sb = smem_u32(smem);
    int tid = threadIdx.x, lane = tid & 31, wid = tid >> 5;
    int wm = wid & 1, wn = wid >> 1;
    int bm = blockIdx.y * 128, bn = blockIdx.x * BN;

    float acc[ACC16 ? 1 : 4][2 * NH][4];
    uint32_t acc16[ACC16 ? 4 : 1][2 * NH][2];
    if (ACC16) {
#pragma unroll
        for (int a = 0; a < 4; a++)
#pragma unroll
            for (int b = 0; b < 2 * NH; b++) { acc16[a][b][0] = 0u; acc16[a][b][1] = 0u; }
    } else {
#pragma unroll
        for (int a = 0; a < 4; a++)
#pragma unroll
            for (int b = 0; b < 2 * NH; b++)
#pragma unroll
                for (int c = 0; c < 4; c++) acc[a][b][c] = 0.f;
    }

    auto load_stage = [&](int kc, int s) {
        uint32_t base = sb + s * STG;
#pragma unroll
        for (int i = 0; i < 4; i++) {
            int idx = tid + i * 256;
            int row = idx >> 3, ch = idx & 7;
            cpa16(base + row * 128 + ((ch ^ (row & 7)) << 4),
                  A + (size_t)(bm + row) * K + kc * 64 + ch * 8);
        }
#pragma unroll
        for (int i = 0; i < BN / 32; i++) {
            int idx = tid + i * 256;
            int row = idx >> 3, ch = idx & 7;
            cpa16(base + 16384 + row * 128 + ((ch ^ (row & 7)) << 4),
                  B + (size_t)(bn + row) * K + kc * 64 + ch * 8);
        }
        CP_COMMIT();
    };

    const int NC = K >> 6;
#pragma unroll
    for (int s = 0; s < NS - 1; s++) load_stage(s, s);

    for (int c = 0; c < NC; c++) {
        if (c + NS - 1 < NC) {
            load_stage(c + NS - 1, (c + NS - 1) % NS);
            asm volatile("cp.async.wait_group %0;" :: "n"(NS - 1) : "memory");
        } else {
            asm volatile("cp.async.wait_group 0;" ::: "memory");
        }
        __syncthreads();

        uint32_t aBase = sb + (c % NS) * STG;
#pragma unroll
        for (int ks = 0; ks < 4; ks++) {
            uint32_t ah[4][4];
#pragma unroll
            for (int mt = 0; mt < 4; mt++) {
                int row = wm * 64 + mt * 16 + (lane & 15);
                int ch = ks * 2 + (lane >> 4);
                LDSM4(ah[mt], aBase + row * 128 + ((ch ^ (row & 7)) << 4));
            }
#pragma unroll
            for (int hh = 0; hh < NH / 2; hh++) {
                uint32_t bh[2][4];
#pragma unroll
                for (int j = 0; j < 2; j++) {
                    int nh = hh * 2 + j;
                    int row = wn * WNB + nh * 16 + (lane & 7) + ((lane >> 4) << 3);
                    int ch = ks * 2 + ((lane >> 3) & 1);
                    LDSM4(bh[j], aBase + 16384 + row * 128 + ((ch ^ (row & 7)) << 4));
                }
#pragma unroll
                for (int mt = 0; mt < 4; mt++) {
#pragma unroll
                    for (int ntl = 0; ntl < 4; ntl++) {
                        if (ACC16)
                            mma_h16(acc16[mt][hh * 4 + ntl], ah[mt],
                                    &bh[ntl >> 1][(ntl & 1) * 2]);
                        else
                            mma_f16(acc[mt][hh * 4 + ntl], ah[mt],
                                    &bh[ntl >> 1][(ntl & 1) * 2]);
                    }
                }
            }
        }
        __syncthreads();
    }

#pragma unroll
    for (int mt = 0; mt < 4; mt++) {
#pragma unroll
        for (int nt = 0; nt < 2 * NH; nt++) {
            int col = bn + wn * WNB + nt * 8 + (lane & 3) * 2;
            int r0 = bm + wm * 64 + mt * 16 + (lane >> 2);
            float bb0 = __ldg(&bias[col]), bb1 = __ldg(&bias[col + 1]);
            float scl = (OUTMODE == 2 && col < qcols) ? 0.125f : 1.f;
#pragma unroll
            for (int half = 0; half < 2; half++) {
                int r = r0 + half * 8;
                float x0, x1;
                if (ACC16) {
                    float2 v = __half22float2(*(__half2*)&acc16[mt][nt][half]);
                    x0 = v.x + bb0; x1 = v.y + bb1;
                } else {
                    x0 = acc[mt][nt][half * 2 + 0] + bb0;
                    x1 = acc[mt][nt][half * 2 + 1] + bb1;
                }
                if (ACT == 1) {
                    x0 = 0.5f * x0 * (1.f + erff(x0 * 0.70710678118654752f));
                    x1 = 0.5f * x1 * (1.f + erff(x1 * 0.70710678118654752f));
                }
                if (OUTMODE == 2) { x0 *= scl; x1 *= scl; }
                if (OUTMODE == 0) {
                    *(float2*)&C[(size_t)r * N + col] = make_float2(x0, x1);
                } else {
                    *(__half2*)&Ch[(size_t)r * N + col] =
                        __float22half2_rn(make_float2(x0, x1));
                }
            }
        }
    }
}

// ---------------- fp16 flash attention: persistent, dynamic tickets --------
// 64-query items, 128 threads. Q pre-scaled by 1/8 in the producing GEMM.
#define ATT_SQ   0
#define ATT_SK   8192
#define ATT_SV   24576
#define ATT_RPB  40960
#define ATT_SMEM 45568
#define ATT_ITEMS 1024   /* 16 bq * 16 heads * 4 batches */

template <int BIAS>
__global__ __launch_bounds__(128) void attn_tc(
    const __half* __restrict__ Qb, int qs,
    const __half* __restrict__ KVb, int kvs, int koff, int voff,
    const float* __restrict__ rpb, __half* __restrict__ Oh)
{
    extern __shared__ char smem[];
    __shared__ int s_item;
    uint32_t sb = smem_u32(smem);
    float* srpb = (float*)(smem + ATT_RPB);
    int tid = threadIdx.x, lane = tid & 31, w = tid >> 5;

    while (true) {
        if (tid == 0) s_item = atomicAdd(&g_tk[BIAS], 1);
        __syncthreads();
        int item = s_item;
        if (item >= ATT_ITEMS) break;
        int bq = item & 15, head = (item >> 4) & 15, b = item >> 8;

        if (BIAS) {
            for (int i = tid; i < 1087; i += 128)
                srpb[i] = __ldg(&rpb[bq * 64 + i]);
        }

        {
            const __half* qsrc = Qb + (size_t)(b * SEQ + bq * 64) * qs + head * HDIM;
#pragma unroll
            for (int i = 0; i < 4; i++) {
                int idx = tid + i * 128;
                int row = idx >> 3, ch = idx & 7;
                cpa16(sb + ATT_SQ + row * 128 + ((ch ^ (row & 7)) << 4),
                      qsrc + (size_t)row * qs + ch * 8);
            }
        }
        auto load_kv = [&](int t, int s) {
            const __half* kb = KVb + (size_t)(b * SEQ + t * 64) * kvs + koff + head * HDIM;
            const __half* vb = KVb + (size_t)(b * SEQ + t * 64) * kvs + voff + head * HDIM;
#pragma unroll
            for (int i = 0; i < 4; i++) {
                int idx = tid + i * 128;
                int row = idx >> 3, ch = idx & 7;
                uint32_t so = row * 128 + ((ch ^ (row & 7)) << 4) + s * 8192;
                cpa16(sb + ATT_SK + so, kb + (size_t)row * kvs + ch * 8);
                cpa16(sb + ATT_SV + so, vb + (size_t)row * kvs + ch * 8);
            }
            CP_COMMIT();
        };
        load_kv(0, 0);

        uint32_t qf[4][4];
        uint32_t O16[8][2];
#pragma unroll
        for (int j = 0; j < 8; j++) { O16[j][0] = 0u; O16[j][1] = 0u; }
        float l0 = 0.f, l1 = 0.f;

        const int qo_lo = w * 16 + (lane >> 2);

        for (int t = 0; t < 16; t++) {
            __syncthreads();
            if (t + 1 < 16) {
                load_kv(t + 1, (t + 1) & 1);
                asm volatile("cp.async.wait_group 1;" ::: "memory");
            } else {
                asm volatile("cp.async.wait_group 0;" ::: "memory");
            }
            __syncthreads();

            if (t == 0) {
#pragma unroll
                for (int ks = 0; ks < 4; ks++) {
                    int row = w * 16 + (lane & 15);
                    int ch = ks * 2 + (lane >> 4);
                    LDSM4(qf[ks], sb + ATT_SQ + row * 128 + ((ch ^ (row & 7)) << 4));
                }
            }

            uint32_t kbase = sb + ATT_SK + (t & 1) * 8192;
            uint32_t vbase = sb + ATT_SV + (t & 1) * 8192;

            uint32_t sc16[8][2];
#pragma unroll
            for (int j = 0; j < 8; j++) { sc16[j][0] = 0u; sc16[j][1] = 0u; }
#pragma unroll
            for (int p = 0; p < 4; p++) {
#pragma unroll
                for (int ks = 0; ks < 4; ks++) {
                    uint32_t kf[4];
                    int row = p * 16 + (lane & 7) + ((lane >> 4) << 3);
                    int ch = ks * 2 + ((lane >> 3) & 1);
                    LDSM4(kf, kbase + row * 128 + ((ch ^ (row & 7)) << 4));
                    mma_h16(sc16[2 * p], qf[ks], kf);
                    mma_h16(sc16[2 * p + 1], qf[ks], kf + 2);
                }
            }

            float sc[8][4];
            float ps0 = 0.f, ps1 = 0.f;
#pragma unroll
            for (int j = 0; j < 8; j++) {
                float2 vlo = __half22float2(*(__half2*)&sc16[j][0]);
                float2 vhi = __half22float2(*(__half2*)&sc16[j][1]);
                float v4[4] = {vlo.x, vlo.y, vhi.x, vhi.y};
                int keyb = t * 64 + 8 * j + 2 * (lane & 3);
#pragma unroll
                for (int e = 0; e < 4; e++) {
                    float s = v4[e];  // Q pre-scaled by 1/8 in GEMM epilogue
                    if (BIAS) {
                        int qo = qo_lo + (e >> 1) * 8;
                        s += srpb[qo - (keyb + (e & 1)) + 1023];
                    }
                    float p = __expf(s);
                    sc[j][e] = p;
                    if ((e >> 1) == 0) ps0 += p; else ps1 += p;
                }
            }
            l0 += ps0; l1 += ps1;

#pragma unroll
            for (int ks = 0; ks < 4; ks++) {
                uint32_t a[4];
                a[0] = packh2(sc[2 * ks][0], sc[2 * ks][1]);
                a[1] = packh2(sc[2 * ks][2], sc[2 * ks][3]);
                a[2] = packh2(sc[2 * ks + 1][0], sc[2 * ks + 1][1]);
                a[3] = packh2(sc[2 * ks + 1][2], sc[2 * ks + 1][3]);
#pragma unroll
                for (int nc = 0; nc < 4; nc++) {
                    uint32_t vf[4];
                    int row = ks * 16 + (lane & 15);
                    int ch = nc * 2 + (lane >> 4);
                    LDSM4T(vf, vbase + row * 128 + ((ch ^ (row & 7)) << 4));
                    mma_h16(O16[2 * nc], a, vf);
                    mma_h16(O16[2 * nc + 1], a, vf + 2);
                }
            }
        }

        l0 += __shfl_xor_sync(0xffffffffu, l0, 1);
        l0 += __shfl_xor_sync(0xffffffffu, l0, 2);
        l1 += __shfl_xor_sync(0xffffffffu, l1, 1);
        l1 += __shfl_xor_sync(0xffffffffu, l1, 2);
        float i0 = 1.f / l0, i1 = 1.f / l1;

        int tok_lo = b * SEQ + bq * 64 + qo_lo;
        size_t base_lo = (size_t)tok_lo * DMODEL + head * HDIM + 2 * (lane & 3);
        size_t base_hi = base_lo + 8 * DMODEL;
#pragma unroll
        for (int j = 0; j < 8; j++) {
            float2 vlo = __half22float2(*(__half2*)&O16[j][0]);
            float2 vhi = __half22float2(*(__half2*)&O16[j][1]);
            *(__half2*)&Oh[base_lo + 8 * j] =
                __float22half2_rn(make_float2(vlo.x * i0, vlo.y * i0));
            *(__half2*)&Oh[base_hi + 8 * j] =
                __float22half2_rn(make_float2(vhi.x * i1, vhi.y * i1));
        }
    }
}

// ---------------- weight convert+transpose: W[K][N] -> fp16 [N][K] ----------
__global__ __launch_bounds__(256) void wconv_t(
    const float* __restrict__ W, __half* __restrict__ out, int K, int N)
{
    __shared__ float s[32][33];
    int tx = threadIdx.x & 31, ty = threadIdx.x >> 5;
    int n0 = blockIdx.x * 32, k0 = blockIdx.y * 32;
#pragma unroll
    for (int i = 0; i < 4; i++)
        s[ty + 8 * i][tx] = W[(size_t)(k0 + ty + 8 * i) * N + n0 + tx];
    __syncthreads();
#pragma unroll
    for (int i = 0; i < 4; i++) {
        int n = ty + 8 * i;
        out[(size_t)(n0 + n) * K + k0 + tx] = __float2half_rn(s[tx][n]);
    }
}

// ---------------- activation convert f32 -> fp16 ----------------
__global__ void conv_act(const float* __restrict__ in, __half* __restrict__ out)
{
    int idx = blockIdx.x * 256 + threadIdx.x;
    float4 v = ((const float4*)in)[idx];
    ((__half2*)out)[idx * 2]     = __float22half2_rn(make_float2(v.x, v.y));
    ((__half2*)out)[idx * 2 + 1] = __float22half2_rn(make_float2(v.z, v.w));
}

// ---------------- step-embed add (+fp16) ----------------
__global__ void add_step_kernel(const float* __restrict__ hidden,
                                const float* __restrict__ se,
                                const int* __restrict__ ts,
                                float* __restrict__ out,
                                __half* __restrict__ o16)
{
    int idx = blockIdx.x * 256 + threadIdx.x;
    int c = ts[0];
    if (c > 19) c = 19;
    float4 h = ((const float4*)hidden)[idx];
    float4 s = ((const float4*)(se + c * DMODEL))[idx & 255];
    float4 o = make_float4(h.x + s.x, h.y + s.y, h.z + s.z, h.w + s.w);
    ((float4*)out)[idx] = o;
    ((__half2*)o16)[idx * 2]     = __float22half2_rn(make_float2(o.x, o.y));
    ((__half2*)o16)[idx * 2 + 1] = __float22half2_rn(make_float2(o.z, o.w));
}

// ---------------- residual + LayerNorm (Bx fp16 delta or f32) ---------------
template <int BXH>
__global__ __launch_bounds__(256) void ln_kernel(
    const float* __restrict__ A, const float* __restrict__ BxF,
    const __half* __restrict__ BxH,
    const float* __restrict__ g, const float* __restrict__ beta,
    float* __restrict__ out, __half* __restrict__ o16)
{
    int row = blockIdx.x, tid = threadIdx.x;
    const float4 va = ((const float4*)(A + (size_t)row * DMODEL))[tid];
    float b0, b1, b2, b3;
    if (BXH) {
        __half2 ha = ((const __half2*)BxH)[(size_t)row * 512 + tid * 2];
        __half2 hb = ((const __half2*)BxH)[(size_t)row * 512 + tid * 2 + 1];
        float2 fa = __half22float2(ha), fb = __half22float2(hb);
        b0 = fa.x; b1 = fa.y; b2 = fb.x; b3 = fb.y;
    } else {
        const float4 vb = ((const float4*)(BxF + (size_t)row * DMODEL))[tid];
        b0 = vb.x; b1 = vb.y; b2 = vb.z; b3 = vb.w;
    }
    float x0 = va.x + b0, x1 = va.y + b1, x2 = va.z + b2, x3 = va.w + b3;

    float s = x0 + x1 + x2 + x3;
    float ss = x0 * x0 + x1 * x1 + x2 * x2 + x3 * x3;
#pragma unroll
    for (int o = 16; o > 0; o >>= 1) {
        s  += __shfl_xor_sync(0xffffffffu, s, o);
        ss += __shfl_xor_sync(0xffffffffu, ss, o);
    }
    __shared__ float sb[16];
    int warp = tid >> 5, lane = tid & 31;
    if (lane == 0) { sb[warp] = s; sb[8 + warp] = ss; }
    __syncthreads();
    if (warp == 0) {
        float s2  = (lane < 8) ? sb[lane] : 0.f;
        float ss2 = (lane < 8) ? sb[8 + lane] : 0.f;
#pragma unroll
        for (int o = 4; o > 0; o >>= 1) {
            s2  += __shfl_xor_sync(0xffffffffu, s2, o);
            ss2 += __shfl_xor_sync(0xffffffffu, ss2, o);
        }
        if (lane == 0) { sb[0] = s2; sb[8] = ss2; }
    }
    __syncthreads();
    float mu  = sb[0] * (1.f / 1024.f);
    float var = sb[8] * (1.f / 1024.f) - mu * mu;
    float rstd = rsqrtf(var + 1e-5f);

    float4 go = ((const float4*)g)[tid];
    float4 bo = ((const float4*)beta)[tid];
    float4 r4;
    r4.x = (x0 - mu) * rstd * go.x + bo.x;
    r4.y = (x1 - mu) * rstd * go.y + bo.y;
    r4.z = (x2 - mu) * rstd * go.z + bo.z;
    r4.w = (x3 - mu) * rstd * go.w + bo.w;
    ((float4*)(out + (size_t)row * DMODEL))[tid] = r4;

    if (o16) {
        size_t base = (size_t)row * DMODEL / 2 + tid * 2;
        ((__half2*)o16)[base]     = __float22half2_rn(make_float2(r4.x, r4.y));
        ((__half2*)o16)[base + 1] = __float22half2_rn(make_float2(r4.z, r4.w));
    }
}

// ---------------- orchestration ----------------
extern "C" void kernel_launch(void* const* d_in, const int* in_sizes, int n_in,
                              void* d_out, int out_size)
{
    const float* hidden = (const float*)d_in[0];
    const float* source = (const float*)d_in[1];
    const int*   tstep  = (const int*)d_in[2];
    const float* sembed = (const float*)d_in[3];
    const float* rpb    = (const float*)d_in[4];
    const float* Wqkv = (const float*)d_in[5],  *bqkv = (const float*)d_in[6];
    const float* Wo   = (const float*)d_in[7],  *bo   = (const float*)d_in[8];
    const float* Wcq  = (const float*)d_in[9],  *bcq  = (const float*)d_in[10];
    const float* Wckv = (const float*)d_in[11], *bckv = (const float*)d_in[12];
    const float* Wco  = (const float*)d_in[13], *bco  = (const float*)d_in[14];
    const float* W1   = (const float*)d_in[15], *b1   = (const float*)d_in[16];
    const float* W2   = (const float*)d_in[17], *b2   = (const float*)d_in[18];
    const float* gs = (const float*)d_in[19], *bts = (const float*)d_in[20];
    const float* gc = (const float*)d_in[21], *btc = (const float*)d_in[22];
    const float* gf = (const float*)d_in[23], *btf = (const float*)d_in[24];
    float* out = (float*)d_out;

    float* ph;
    __half *pd16, *pa16, *ps16, *pff16, *pff2, *pw16;
    cudaGetSymbolAddress((void**)&ph,    g_h);
    cudaGetSymbolAddress((void**)&pd16,  g_d16);
    cudaGetSymbolAddress((void**)&pa16,  g_a16);
    cudaGetSymbolAddress((void**)&ps16,  g_s16);
    cudaGetSymbolAddress((void**)&pff16, g_ff16);
    cudaGetSymbolAddress((void**)&pff2,  g_ff2);
    cudaGetSymbolAddress((void**)&pw16,  g_w16);

    __half* pqkv16 = pff16;
    __half* pcq16  = pff2;
    __half* pckv16 = pff2 + 4194304;

    const int SM_128 = 3 * 32768;
    const int SM_256 = 2 * 49152;
    cudaFuncSetAttribute(gemm_mma<0,2,2,256,1>, cudaFuncAttributeMaxDynamicSharedMemorySize, SM_256);
    cudaFuncSetAttribute(gemm_mma<0,2,3,128,1>, cudaFuncAttributeMaxDynamicSharedMemorySize, SM_128);
    cudaFuncSetAttribute(gemm_mma<0,3,3,128,0>, cudaFuncAttributeMaxDynamicSharedMemorySize, SM_128);
    cudaFuncSetAttribute(gemm_mma<1,2,2,256,0>, cudaFuncAttributeMaxDynamicSharedMemorySize, SM_256);
    cudaFuncSetAttribute(attn_tc<0>, cudaFuncAttributeMaxDynamicSharedMemorySize, ATT_SMEM);
    cudaFuncSetAttribute(attn_tc<1>, cudaFuncAttributeMaxDynamicSharedMemorySize, ATT_SMEM);

    static cudaStream_t s2 = nullptr;
    static cudaEvent_t evFork = nullptr, evQ = nullptr, evW = nullptr, evJoin = nullptr;
    if (!s2) {
        cudaStreamCreateWithFlags(&s2, cudaStreamNonBlocking);
        cudaEventCreateWithFlags(&evFork, cudaEventDisableTiming);
        cudaEventCreateWithFlags(&evQ,    cudaEventDisableTiming);
        cudaEventCreateWithFlags(&evW,    cudaEventDisableTiming);
        cudaEventCreateWithFlags(&evJoin, cudaEventDisableTiming);
    }

    // ---- fork immediately; main does tickets+add_step while s2 converts Wqkv ----
    cudaEventRecord(evFork, 0);
    cudaStreamWaitEvent(s2, evFork, 0);

    reset_tk<<<1, 32>>>();
    add_step_kernel<<<TOKENS * DMODEL / 1024, 256>>>(hidden, sembed, tstep, ph, pa16);

    wconv_t<<<dim3(3072/32, 1024/32), 256, 0, s2>>>(Wqkv, pw16 + OFF_QKV, 1024, 3072);
    cudaEventRecord(evQ, s2);
    wconv_t<<<dim3(1024/32, 1024/32), 256, 0, s2>>>(Wo,   pw16 + OFF_O,   1024, 1024);
    wconv_t<<<dim3(1024/32, 1024/32), 256, 0, s2>>>(Wcq,  pw16 + OFF_CQ,  1024, 1024);
    wconv_t<<<dim3(2048/32, 1024/32), 256, 0, s2>>>(Wckv, pw16 + OFF_CKV, 1024, 2048);
    wconv_t<<<dim3(1024/32, 1024/32), 256, 0, s2>>>(Wco,  pw16 + OFF_CO,  1024, 1024);
    wconv_t<<<dim3(4096/32, 1024/32), 256, 0, s2>>>(W1,   pw16 + OFF_W1,  1024, 4096);
    wconv_t<<<dim3(1024/32, 4096/32), 256, 0, s2>>>(W2,   pw16 + OFF_W2,  4096, 1024);
    cudaEventRecord(evW, s2);
    conv_act<<<TOKENS * DMODEL / 1024, 256, 0, s2>>>(source, ps16);
    gemm_mma<0,2,2,256,1><<<dim3(2048/256, TOKENS/128), 256, SM_256, s2>>>(
        ps16, pw16 + OFF_CKV, bckv, nullptr, pckv16, TOKENS, 2048, 1024, 0);
    cudaEventRecord(evJoin, s2);

    // ---- main: QKV (q cols pre-scaled by 1/8) -> self-attn ----
    cudaStreamWaitEvent(0, evQ, 0);
    gemm_mma<0,2,3,128,1><<<dim3(3072/128, TOKENS/128), 256, SM_128>>>(
        pa16, pw16 + OFF_QKV, bqkv, nullptr, pqkv16, TOKENS, 3072, 1024, 1024);

    attn_tc<1><<<740, 128, ATT_SMEM>>>(pqkv16, 3072, pqkv16, 3072, 1024, 2048, rpb, pa16);

    cudaStreamWaitEvent(0, evW, 0);
    gemm_mma<0,3,3,128,0><<<dim3(1024/128, TOKENS/128), 256, SM_128>>>(
        pa16, pw16 + OFF_O, bo, nullptr, pd16, TOKENS, 1024, 1024, 0);
    ln_kernel<1><<<TOKENS, 256>>>(ph, nullptr, pd16, gs, bts, ph, pa16);

    gemm_mma<0,2,3,128,1><<<dim3(1024/128, TOKENS/128), 256, SM_128>>>(
        pa16, pw16 + OFF_CQ, bcq, nullptr, pcq16, TOKENS, 1024, 1024, 1024);

    cudaStreamWaitEvent(0, evJoin, 0);
    attn_tc<0><<<740, 128, ATT_SMEM>>>(pcq16, 1024, pckv16, 2048, 0, 1024, rpb, pa16);

    gemm_mma<0,3,3,128,0><<<dim3(1024/128, TOKENS/128), 256, SM_128>>>(
        pa16, pw16 + OFF_CO, bco, nullptr, pd16, TOKENS, 1024, 1024, 0);
    ln_kernel<1><<<TOKENS, 256>>>(ph, nullptr, pd16, gc, btc, ph, pa16);

    gemm_mma<1,2,2,256,0><<<dim3(4096/256, TOKENS/128), 256, SM_256>>>(
        pa16, pw16 + OFF_W1, b1, nullptr, pff16, TOKENS, 4096, 1024, 0);
    gemm_mma<0,3,3,128,0><<<dim3(1024/128, TOKENS/128), 256, SM_128>>>(
        pff16, pw16 + OFF_W2, b2, nullptr, pd16, TOKENS, 1024, 4096, 0);
    ln_kernel<1><<<TOKENS, 256>>>(ph, nullptr, pd16, gf, btf, out, nullptr);
}

// round 13
// speedup vs baseline: 1.0353x; 1.0353x over previous
#include <cuda_runtime.h>
#include <cuda_fp16.h>
#include <cstdint>
#include <math.h>

#define TOKENS 4096
#define DMODEL 1024
#define SEQ    1024
#define NHEAD  16
#define HDIM   64
#define DFF_   4096

// ---------------- scratch (device globals: allocation-free) ----------------
__device__ float g_h[TOKENS * DMODEL];
__device__ __half g_d16[TOKENS * DMODEL];    // fp16 GEMM delta (Wo/Co/W2 out)
__device__ __half g_a16[TOKENS * DMODEL];
__device__ __half g_s16[TOKENS * DMODEL];
__device__ __half g_ff16[TOKENS * DFF_];     // ff fp16; also qkv fp16
__device__ __half g_ff2[TOKENS * DFF_];      // cq fp16 + ckv fp16
__device__ __half g_w16[16777216];

#define OFF_QKV 0
#define OFF_O   3145728
#define OFF_CQ  4194304
#define OFF_CKV 5242880
#define OFF_CO  7340032
#define OFF_W1  8388608
#define OFF_W2  12582912

// ---------------- helpers ----------------
__device__ __forceinline__ uint32_t smem_u32(const void* p) {
    uint32_t a;
    asm("{ .reg .u64 t; cvta.to.shared.u64 t, %1; cvt.u32.u64 %0, t; }" : "=r"(a) : "l"(p));
    return a;
}
__device__ __forceinline__ void cpa16(uint32_t d, const void* g) {
    asm volatile("cp.async.cg.shared.global [%0], [%1], 16;" :: "r"(d), "l"(g));
}
#define CP_COMMIT() asm volatile("cp.async.commit_group;" ::: "memory")
#define LDSM4(r, a) \
    asm volatile("ldmatrix.sync.aligned.m8n8.x4.shared.b16 {%0,%1,%2,%3}, [%4];" \
        : "=r"((r)[0]), "=r"((r)[1]), "=r"((r)[2]), "=r"((r)[3]) : "r"(a))
#define LDSM4T(r, a) \
    asm volatile("ldmatrix.sync.aligned.m8n8.x4.trans.shared.b16 {%0,%1,%2,%3}, [%4];" \
        : "=r"((r)[0]), "=r"((r)[1]), "=r"((r)[2]), "=r"((r)[3]) : "r"(a))

__device__ __forceinline__ void mma_f16(float* d, const uint32_t* a, const uint32_t* b) {
    asm volatile("mma.sync.aligned.m16n8k16.row.col.f32.f16.f16.f32 "
                 "{%0,%1,%2,%3}, {%4,%5,%6,%7}, {%8,%9}, {%0,%1,%2,%3};"
                 : "+f"(d[0]), "+f"(d[1]), "+f"(d[2]), "+f"(d[3])
                 : "r"(a[0]), "r"(a[1]), "r"(a[2]), "r"(a[3]), "r"(b[0]), "r"(b[1]));
}
__device__ __forceinline__ void mma_h16(uint32_t* d, const uint32_t* a, const uint32_t* b) {
    asm volatile("mma.sync.aligned.m16n8k16.row.col.f16.f16.f16.f16 "
                 "{%0,%1}, {%2,%3,%4,%5}, {%6,%7}, {%0,%1};"
                 : "+r"(d[0]), "+r"(d[1])
                 : "r"(a[0]), "r"(a[1]), "r"(a[2]), "r"(a[3]), "r"(b[0]), "r"(b[1]));
}
__device__ __forceinline__ uint32_t packh2(float a, float b) {
    __half2 t = __float22half2_rn(make_float2(a, b));
    return *(uint32_t*)&t;
}

// ---------------- fp16 single-pass HMMA GEMM ----------------
// OUTMODE: 0 = f32 out; 1 = GELU + fp16 out; 2 = fp16 out (qcols scaled 1/8); 3 = fp16 out
template <int ACT, int OUTMODE, int NS, int BN, int ACC16>
__global__ __launch_bounds__(256) void gemm_mma(
    const __half* __restrict__ A, const __half* __restrict__ B,
    const float* __restrict__ bias, float* __restrict__ C,
    __half* __restrict__ Ch, int M, int N, int K, int qcols)
{
    constexpr int WNB = (BN == 256) ? 64 : 32;
    constexpr int NH  = WNB / 16;
    constexpr int B_BYTES = BN * 128;
    constexpr int STG = 16384 + B_BYTES;

    extern __shared__ char smem[];
    uint32_t sb = smem_u32(smem);
    int tid = threadIdx.x, lane = tid & 31, wid = tid >> 5;
    int wm = wid & 1, wn = wid >> 1;
    int bm = blockIdx.y * 128, bn = blockIdx.x * BN;

    float acc[ACC16 ? 1 : 4][2 * NH][4];
    uint32_t acc16[ACC16 ? 4 : 1][2 * NH][2];
    if (ACC16) {
#pragma unroll
        for (int a = 0; a < 4; a++)
#pragma unroll
            for (int b = 0; b < 2 * NH; b++) { acc16[a][b][0] = 0u; acc16[a][b][1] = 0u; }
    } else {
#pragma unroll
        for (int a = 0; a < 4; a++)
#pragma unroll
            for (int b = 0; b < 2 * NH; b++)
#pragma unroll
                for (int c = 0; c < 4; c++) acc[a][b][c] = 0.f;
    }

    auto load_stage = [&](int kc, int s) {
        uint32_t base = sb + s * STG;
#pragma unroll
        for (int i = 0; i < 4; i++) {
            int idx = tid + i * 256;
            int row = idx >> 3, ch = idx & 7;
            cpa16(base + row * 128 + ((ch ^ (row & 7)) << 4),
                  A + (size_t)(bm + row) * K + kc * 64 + ch * 8);
        }
#pragma unroll
        for (int i = 0; i < BN / 32; i++) {
            int idx = tid + i * 256;
            int row = idx >> 3, ch = idx & 7;
            cpa16(base + 16384 + row * 128 + ((ch ^ (row & 7)) << 4),
                  B + (size_t)(bn + row) * K + kc * 64 + ch * 8);
        }
        CP_COMMIT();
    };

    const int NC = K >> 6;
#pragma unroll
    for (int s = 0; s < NS - 1; s++) load_stage(s, s);

    for (int c = 0; c < NC; c++) {
        if (c + NS - 1 < NC) {
            load_stage(c + NS - 1, (c + NS - 1) % NS);
            asm volatile("cp.async.wait_group %0;" :: "n"(NS - 1) : "memory");
        } else {
            asm volatile("cp.async.wait_group 0;" ::: "memory");
        }
        __syncthreads();

        uint32_t aBase = sb + (c % NS) * STG;
#pragma unroll
        for (int ks = 0; ks < 4; ks++) {
            uint32_t ah[4][4];
#pragma unroll
            for (int mt = 0; mt < 4; mt++) {
                int row = wm * 64 + mt * 16 + (lane & 15);
                int ch = ks * 2 + (lane >> 4);
                LDSM4(ah[mt], aBase + row * 128 + ((ch ^ (row & 7)) << 4));
            }
#pragma unroll
            for (int hh = 0; hh < NH / 2; hh++) {
                uint32_t bh[2][4];
#pragma unroll
                for (int j = 0; j < 2; j++) {
                    int nh = hh * 2 + j;
                    int row = wn * WNB + nh * 16 + (lane & 7) + ((lane >> 4) << 3);
                    int ch = ks * 2 + ((lane >> 3) & 1);
                    LDSM4(bh[j], aBase + 16384 + row * 128 + ((ch ^ (row & 7)) << 4));
                }
#pragma unroll
                for (int mt = 0; mt < 4; mt++) {
#pragma unroll
                    for (int ntl = 0; ntl < 4; ntl++) {
                        if (ACC16)
                            mma_h16(acc16[mt][hh * 4 + ntl], ah[mt],
                                    &bh[ntl >> 1][(ntl & 1) * 2]);
                        else
                            mma_f16(acc[mt][hh * 4 + ntl], ah[mt],
                                    &bh[ntl >> 1][(ntl & 1) * 2]);
                    }
                }
            }
        }
        __syncthreads();
    }

#pragma unroll
    for (int mt = 0; mt < 4; mt++) {
#pragma unroll
        for (int nt = 0; nt < 2 * NH; nt++) {
            int col = bn + wn * WNB + nt * 8 + (lane & 3) * 2;
            int r0 = bm + wm * 64 + mt * 16 + (lane >> 2);
            float bb0 = __ldg(&bias[col]), bb1 = __ldg(&bias[col + 1]);
            float scl = (OUTMODE == 2 && col < qcols) ? 0.125f : 1.f;
#pragma unroll
            for (int half = 0; half < 2; half++) {
                int r = r0 + half * 8;
                float x0, x1;
                if (ACC16) {
                    float2 v = __half22float2(*(__half2*)&acc16[mt][nt][half]);
                    x0 = v.x + bb0; x1 = v.y + bb1;
                } else {
                    x0 = acc[mt][nt][half * 2 + 0] + bb0;
                    x1 = acc[mt][nt][half * 2 + 1] + bb1;
                }
                if (ACT == 1) {
                    x0 = 0.5f * x0 * (1.f + erff(x0 * 0.70710678118654752f));
                    x1 = 0.5f * x1 * (1.f + erff(x1 * 0.70710678118654752f));
                }
                if (OUTMODE == 2) { x0 *= scl; x1 *= scl; }
                if (OUTMODE == 0) {
                    *(float2*)&C[(size_t)r * N + col] = make_float2(x0, x1);
                } else {
                    *(__half2*)&Ch[(size_t)r * N + col] =
                        __float22half2_rn(make_float2(x0, x1));
                }
            }
        }
    }
}

// ---------------- fp16 flash attention: static grid, 64-query blocks -------
// Q pre-scaled by 1/8 in the producing GEMM epilogue.
#define ATT_SQ   0
#define ATT_SK   8192
#define ATT_SV   24576
#define ATT_RPB  40960
#define ATT_SMEM 45568

template <int BIAS>
__global__ __launch_bounds__(128) void attn_tc(
    const __half* __restrict__ Qb, int qs,
    const __half* __restrict__ KVb, int kvs, int koff, int voff,
    const float* __restrict__ rpb, __half* __restrict__ Oh)
{
    extern __shared__ char smem[];
    uint32_t sb = smem_u32(smem);
    float* srpb = (float*)(smem + ATT_RPB);
    int tid = threadIdx.x, lane = tid & 31, w = tid >> 5;
    int bq = blockIdx.x, head = blockIdx.y, b = blockIdx.z;

    if (BIAS) {
        for (int i = tid; i < 1087; i += 128)
            srpb[i] = __ldg(&rpb[bq * 64 + i]);
    }

    {
        const __half* qsrc = Qb + (size_t)(b * SEQ + bq * 64) * qs + head * HDIM;
#pragma unroll
        for (int i = 0; i < 4; i++) {
            int idx = tid + i * 128;
            int row = idx >> 3, ch = idx & 7;
            cpa16(sb + ATT_SQ + row * 128 + ((ch ^ (row & 7)) << 4),
                  qsrc + (size_t)row * qs + ch * 8);
        }
    }
    auto load_kv = [&](int t, int s) {
        const __half* kb = KVb + (size_t)(b * SEQ + t * 64) * kvs + koff + head * HDIM;
        const __half* vb = KVb + (size_t)(b * SEQ + t * 64) * kvs + voff + head * HDIM;
#pragma unroll
        for (int i = 0; i < 4; i++) {
            int idx = tid + i * 128;
            int row = idx >> 3, ch = idx & 7;
            uint32_t so = row * 128 + ((ch ^ (row & 7)) << 4) + s * 8192;
            cpa16(sb + ATT_SK + so, kb + (size_t)row * kvs + ch * 8);
            cpa16(sb + ATT_SV + so, vb + (size_t)row * kvs + ch * 8);
        }
        CP_COMMIT();
    };
    load_kv(0, 0);

    uint32_t qf[4][4];
    uint32_t O16[8][2];
#pragma unroll
    for (int j = 0; j < 8; j++) { O16[j][0] = 0u; O16[j][1] = 0u; }
    float l0 = 0.f, l1 = 0.f;

    const int qo_lo = w * 16 + (lane >> 2);

    for (int t = 0; t < 16; t++) {
        __syncthreads();
        if (t + 1 < 16) {
            load_kv(t + 1, (t + 1) & 1);
            asm volatile("cp.async.wait_group 1;" ::: "memory");
        } else {
            asm volatile("cp.async.wait_group 0;" ::: "memory");
        }
        __syncthreads();

        if (t == 0) {
#pragma unroll
            for (int ks = 0; ks < 4; ks++) {
                int row = w * 16 + (lane & 15);
                int ch = ks * 2 + (lane >> 4);
                LDSM4(qf[ks], sb + ATT_SQ + row * 128 + ((ch ^ (row & 7)) << 4));
            }
        }

        uint32_t kbase = sb + ATT_SK + (t & 1) * 8192;
        uint32_t vbase = sb + ATT_SV + (t & 1) * 8192;

        uint32_t sc16[8][2];
#pragma unroll
        for (int j = 0; j < 8; j++) { sc16[j][0] = 0u; sc16[j][1] = 0u; }
#pragma unroll
        for (int p = 0; p < 4; p++) {
#pragma unroll
            for (int ks = 0; ks < 4; ks++) {
                uint32_t kf[4];
                int row = p * 16 + (lane & 7) + ((lane >> 4) << 3);
                int ch = ks * 2 + ((lane >> 3) & 1);
                LDSM4(kf, kbase + row * 128 + ((ch ^ (row & 7)) << 4));
                mma_h16(sc16[2 * p], qf[ks], kf);
                mma_h16(sc16[2 * p + 1], qf[ks], kf + 2);
            }
        }

        float sc[8][4];
        float ps0 = 0.f, ps1 = 0.f;
#pragma unroll
        for (int j = 0; j < 8; j++) {
            float2 vlo = __half22float2(*(__half2*)&sc16[j][0]);
            float2 vhi = __half22float2(*(__half2*)&sc16[j][1]);
            float v4[4] = {vlo.x, vlo.y, vhi.x, vhi.y};
            int keyb = t * 64 + 8 * j + 2 * (lane & 3);
#pragma unroll
            for (int e = 0; e < 4; e++) {
                float s = v4[e];  // Q pre-scaled by 1/8 in GEMM epilogue
                if (BIAS) {
                    int qo = qo_lo + (e >> 1) * 8;
                    s += srpb[qo - (keyb + (e & 1)) + 1023];
                }
                float p = __expf(s);
                sc[j][e] = p;
                if ((e >> 1) == 0) ps0 += p; else ps1 += p;
            }
        }
        l0 += ps0; l1 += ps1;

#pragma unroll
        for (int ks = 0; ks < 4; ks++) {
            uint32_t a[4];
            a[0] = packh2(sc[2 * ks][0], sc[2 * ks][1]);
            a[1] = packh2(sc[2 * ks][2], sc[2 * ks][3]);
            a[2] = packh2(sc[2 * ks + 1][0], sc[2 * ks + 1][1]);
            a[3] = packh2(sc[2 * ks + 1][2], sc[2 * ks + 1][3]);
#pragma unroll
            for (int nc = 0; nc < 4; nc++) {
                uint32_t vf[4];
                int row = ks * 16 + (lane & 15);
                int ch = nc * 2 + (lane >> 4);
                LDSM4T(vf, vbase + row * 128 + ((ch ^ (row & 7)) << 4));
                mma_h16(O16[2 * nc], a, vf);
                mma_h16(O16[2 * nc + 1], a, vf + 2);
            }
        }
    }

    l0 += __shfl_xor_sync(0xffffffffu, l0, 1);
    l0 += __shfl_xor_sync(0xffffffffu, l0, 2);
    l1 += __shfl_xor_sync(0xffffffffu, l1, 1);
    l1 += __shfl_xor_sync(0xffffffffu, l1, 2);
    float i0 = 1.f / l0, i1 = 1.f / l1;

    int tok_lo = b * SEQ + bq * 64 + qo_lo;
    size_t base_lo = (size_t)tok_lo * DMODEL + head * HDIM + 2 * (lane & 3);
    size_t base_hi = base_lo + 8 * DMODEL;
#pragma unroll
    for (int j = 0; j < 8; j++) {
        float2 vlo = __half22float2(*(__half2*)&O16[j][0]);
        float2 vhi = __half22float2(*(__half2*)&O16[j][1]);
        *(__half2*)&Oh[base_lo + 8 * j] =
            __float22half2_rn(make_float2(vlo.x * i0, vlo.y * i0));
        *(__half2*)&Oh[base_hi + 8 * j] =
            __float22half2_rn(make_float2(vhi.x * i1, vhi.y * i1));
    }
}

// ---------------- weight convert+transpose: W[K][N] -> fp16 [N][K] ----------
__global__ __launch_bounds__(256) void wconv_t(
    const float* __restrict__ W, __half* __restrict__ out, int K, int N)
{
    __shared__ float s[32][33];
    int tx = threadIdx.x & 31, ty = threadIdx.x >> 5;
    int n0 = blockIdx.x * 32, k0 = blockIdx.y * 32;
#pragma unroll
    for (int i = 0; i < 4; i++)
        s[ty + 8 * i][tx] = W[(size_t)(k0 + ty + 8 * i) * N + n0 + tx];
    __syncthreads();
#pragma unroll
    for (int i = 0; i < 4; i++) {
        int n = ty + 8 * i;
        out[(size_t)(n0 + n) * K + k0 + tx] = __float2half_rn(s[tx][n]);
    }
}

// ---------------- activation convert f32 -> fp16 ----------------
__global__ void conv_act(const float* __restrict__ in, __half* __restrict__ out)
{
    int idx = blockIdx.x * 256 + threadIdx.x;
    float4 v = ((const float4*)in)[idx];
    ((__half2*)out)[idx * 2]     = __float22half2_rn(make_float2(v.x, v.y));
    ((__half2*)out)[idx * 2 + 1] = __float22half2_rn(make_float2(v.z, v.w));
}

// ---------------- step-embed add (+fp16) ----------------
__global__ void add_step_kernel(const float* __restrict__ hidden,
                                const float* __restrict__ se,
                                const int* __restrict__ ts,
                                float* __restrict__ out,
                                __half* __restrict__ o16)
{
    int idx = blockIdx.x * 256 + threadIdx.x;
    int c = ts[0];
    if (c > 19) c = 19;
    float4 h = ((const float4*)hidden)[idx];
    float4 s = ((const float4*)(se + c * DMODEL))[idx & 255];
    float4 o = make_float4(h.x + s.x, h.y + s.y, h.z + s.z, h.w + s.w);
    ((float4*)out)[idx] = o;
    ((__half2*)o16)[idx * 2]     = __float22half2_rn(make_float2(o.x, o.y));
    ((__half2*)o16)[idx * 2 + 1] = __float22half2_rn(make_float2(o.z, o.w));
}

// ---------------- residual + LayerNorm (Bx fp16 delta) ----------------------
__global__ __launch_bounds__(256) void ln_kernel(
    const float* __restrict__ A, const __half* __restrict__ BxH,
    const float* __restrict__ g, const float* __restrict__ beta,
    float* __restrict__ out, __half* __restrict__ o16)
{
    int row = blockIdx.x, tid = threadIdx.x;
    const float4 va = ((const float4*)(A + (size_t)row * DMODEL))[tid];
    __half2 ha = ((const __half2*)BxH)[(size_t)row * 512 + tid * 2];
    __half2 hb = ((const __half2*)BxH)[(size_t)row * 512 + tid * 2 + 1];
    float2 fa = __half22float2(ha), fb = __half22float2(hb);
    float x0 = va.x + fa.x, x1 = va.y + fa.y, x2 = va.z + fb.x, x3 = va.w + fb.y;

    float s = x0 + x1 + x2 + x3;
    float ss = x0 * x0 + x1 * x1 + x2 * x2 + x3 * x3;
#pragma unroll
    for (int o = 16; o > 0; o >>= 1) {
        s  += __shfl_xor_sync(0xffffffffu, s, o);
        ss += __shfl_xor_sync(0xffffffffu, ss, o);
    }
    __shared__ float sb[16];
    int warp = tid >> 5, lane = tid & 31;
    if (lane == 0) { sb[warp] = s; sb[8 + warp] = ss; }
    __syncthreads();
    if (warp == 0) {
        float s2  = (lane < 8) ? sb[lane] : 0.f;
        float ss2 = (lane < 8) ? sb[8 + lane] : 0.f;
#pragma unroll
        for (int o = 4; o > 0; o >>= 1) {
            s2  += __shfl_xor_sync(0xffffffffu, s2, o);
            ss2 += __shfl_xor_sync(0xffffffffu, ss2, o);
        }
        if (lane == 0) { sb[0] = s2; sb[8] = ss2; }
    }
    __syncthreads();
    float mu  = sb[0] * (1.f / 1024.f);
    float var = sb[8] * (1.f / 1024.f) - mu * mu;
    float rstd = rsqrtf(var + 1e-5f);

    float4 go = ((const float4*)g)[tid];
    float4 bo = ((const float4*)beta)[tid];
    float4 r4;
    r4.x = (x0 - mu) * rstd * go.x + bo.x;
    r4.y = (x1 - mu) * rstd * go.y + bo.y;
    r4.z = (x2 - mu) * rstd * go.z + bo.z;
    r4.w = (x3 - mu) * rstd * go.w + bo.w;
    ((float4*)(out + (size_t)row * DMODEL))[tid] = r4;

    if (o16) {
        size_t base = (size_t)row * DMODEL / 2 + tid * 2;
        ((__half2*)o16)[base]     = __float22half2_rn(make_float2(r4.x, r4.y));
        ((__half2*)o16)[base + 1] = __float22half2_rn(make_float2(r4.z, r4.w));
    }
}

// ---------------- orchestration ----------------
extern "C" void kernel_launch(void* const* d_in, const int* in_sizes, int n_in,
                              void* d_out, int out_size)
{
    const float* hidden = (const float*)d_in[0];
    const float* source = (const float*)d_in[1];
    const int*   tstep  = (const int*)d_in[2];
    const float* sembed = (const float*)d_in[3];
    const float* rpb    = (const float*)d_in[4];
    const float* Wqkv = (const float*)d_in[5],  *bqkv = (const float*)d_in[6];
    const float* Wo   = (const float*)d_in[7],  *bo   = (const float*)d_in[8];
    const float* Wcq  = (const float*)d_in[9],  *bcq  = (const float*)d_in[10];
    const float* Wckv = (const float*)d_in[11], *bckv = (const float*)d_in[12];
    const float* Wco  = (const float*)d_in[13], *bco  = (const float*)d_in[14];
    const float* W1   = (const float*)d_in[15], *b1   = (const float*)d_in[16];
    const float* W2   = (const float*)d_in[17], *b2   = (const float*)d_in[18];
    const float* gs = (const float*)d_in[19], *bts = (const float*)d_in[20];
    const float* gc = (const float*)d_in[21], *btc = (const float*)d_in[22];
    const float* gf = (const float*)d_in[23], *btf = (const float*)d_in[24];
    float* out = (float*)d_out;

    float* ph;
    __half *pd16, *pa16, *ps16, *pff16, *pff2, *pw16;
    cudaGetSymbolAddress((void**)&ph,    g_h);
    cudaGetSymbolAddress((void**)&pd16,  g_d16);
    cudaGetSymbolAddress((void**)&pa16,  g_a16);
    cudaGetSymbolAddress((void**)&ps16,  g_s16);
    cudaGetSymbolAddress((void**)&pff16, g_ff16);
    cudaGetSymbolAddress((void**)&pff2,  g_ff2);
    cudaGetSymbolAddress((void**)&pw16,  g_w16);

    __half* pqkv16 = pff16;
    __half* pcq16  = pff2;
    __half* pckv16 = pff2 + 4194304;

    const int SM_128 = 3 * 32768;
    const int SM_256 = 2 * 49152;
    cudaFuncSetAttribute(gemm_mma<0,2,2,256,1>, cudaFuncAttributeMaxDynamicSharedMemorySize, SM_256);
    cudaFuncSetAttribute(gemm_mma<0,2,3,128,1>, cudaFuncAttributeMaxDynamicSharedMemorySize, SM_128);
    cudaFuncSetAttribute(gemm_mma<0,3,3,128,0>, cudaFuncAttributeMaxDynamicSharedMemorySize, SM_128);
    cudaFuncSetAttribute(gemm_mma<1,2,2,256,0>, cudaFuncAttributeMaxDynamicSharedMemorySize, SM_256);
    cudaFuncSetAttribute(attn_tc<0>, cudaFuncAttributeMaxDynamicSharedMemorySize, ATT_SMEM);
    cudaFuncSetAttribute(attn_tc<1>, cudaFuncAttributeMaxDynamicSharedMemorySize, ATT_SMEM);

    static cudaStream_t s2 = nullptr;
    static cudaEvent_t evFork = nullptr, evQ = nullptr, evW = nullptr, evJoin = nullptr;
    if (!s2) {
        cudaStreamCreateWithFlags(&s2, cudaStreamNonBlocking);
        cudaEventCreateWithFlags(&evFork, cudaEventDisableTiming);
        cudaEventCreateWithFlags(&evQ,    cudaEventDisableTiming);
        cudaEventCreateWithFlags(&evW,    cudaEventDisableTiming);
        cudaEventCreateWithFlags(&evJoin, cudaEventDisableTiming);
    }

    // ---- fork immediately: s2 converts weights while main does add_step ----
    cudaEventRecord(evFork, 0);
    cudaStreamWaitEvent(s2, evFork, 0);

    add_step_kernel<<<TOKENS * DMODEL / 1024, 256>>>(hidden, sembed, tstep, ph, pa16);

    wconv_t<<<dim3(3072/32, 1024/32), 256, 0, s2>>>(Wqkv, pw16 + OFF_QKV, 1024, 3072);
    cudaEventRecord(evQ, s2);
    wconv_t<<<dim3(1024/32, 1024/32), 256, 0, s2>>>(Wo,   pw16 + OFF_O,   1024, 1024);
    wconv_t<<<dim3(1024/32, 1024/32), 256, 0, s2>>>(Wcq,  pw16 + OFF_CQ,  1024, 1024);
    wconv_t<<<dim3(2048/32, 1024/32), 256, 0, s2>>>(Wckv, pw16 + OFF_CKV, 1024, 2048);
    wconv_t<<<dim3(1024/32, 1024/32), 256, 0, s2>>>(Wco,  pw16 + OFF_CO,  1024, 1024);
    wconv_t<<<dim3(4096/32, 1024/32), 256, 0, s2>>>(W1,   pw16 + OFF_W1,  1024, 4096);
    wconv_t<<<dim3(1024/32, 4096/32), 256, 0, s2>>>(W2,   pw16 + OFF_W2,  4096, 1024);
    cudaEventRecord(evW, s2);
    conv_act<<<TOKENS * DMODEL / 1024, 256, 0, s2>>>(source, ps16);
    gemm_mma<0,2,2,256,1><<<dim3(2048/256, TOKENS/128), 256, SM_256, s2>>>(
        ps16, pw16 + OFF_CKV, bckv, nullptr, pckv16, TOKENS, 2048, 1024, 0);
    cudaEventRecord(evJoin, s2);

    // ---- main: QKV (q cols pre-scaled 1/8) -> self-attn ----
    cudaStreamWaitEvent(0, evQ, 0);
    gemm_mma<0,2,3,128,1><<<dim3(3072/128, TOKENS/128), 256, SM_128>>>(
        pa16, pw16 + OFF_QKV, bqkv, nullptr, pqkv16, TOKENS, 3072, 1024, 1024);

    dim3 ga(SEQ / 64, NHEAD, 4);
    attn_tc<1><<<ga, 128, ATT_SMEM>>>(pqkv16, 3072, pqkv16, 3072, 1024, 2048, rpb, pa16);

    cudaStreamWaitEvent(0, evW, 0);
    gemm_mma<0,3,3,128,0><<<dim3(1024/128, TOKENS/128), 256, SM_128>>>(
        pa16, pw16 + OFF_O, bo, nullptr, pd16, TOKENS, 1024, 1024, 0);
    ln_kernel<<<TOKENS, 256>>>(ph, pd16, gs, bts, ph, pa16);

    gemm_mma<0,2,3,128,1><<<dim3(1024/128, TOKENS/128), 256, SM_128>>>(
        pa16, pw16 + OFF_CQ, bcq, nullptr, pcq16, TOKENS, 1024, 1024, 1024);

    cudaStreamWaitEvent(0, evJoin, 0);
    attn_tc<0><<<ga, 128, ATT_SMEM>>>(pcq16, 1024, pckv16, 2048, 0, 1024, rpb, pa16);

    gemm_mma<0,3,3,128,0><<<dim3(1024/128, TOKENS/128), 256, SM_128>>>(
        pa16, pw16 + OFF_CO, bco, nullptr, pd16, TOKENS, 1024, 1024, 0);
    ln_kernel<<<TOKENS, 256>>>(ph, pd16, gc, btc, ph, pa16);

    gemm_mma<1,2,2,256,0><<<dim3(4096/256, TOKENS/128), 256, SM_256>>>(
        pa16, pw16 + OFF_W1, b1, nullptr, pff16, TOKENS, 4096, 1024, 0);
    gemm_mma<0,3,3,128,0><<<dim3(1024/128, TOKENS/128), 256, SM_128>>>(
        pff16, pw16 + OFF_W2, b2, nullptr, pd16, TOKENS, 1024, 4096, 0);
    ln_kernel<<<TOKENS, 256>>>(ph, pd16, gf, btf, out, nullptr);
}

// round 14
// speedup vs baseline: 1.0849x; 1.0479x over previous
#include <cuda_runtime.h>
#include <cuda_fp16.h>
#include <cstdint>
#include <math.h>

#define TOKENS 4096
#define DMODEL 1024
#define SEQ    1024
#define NHEAD  16
#define HDIM   64
#define DFF_   4096

// ---------------- scratch (device globals: allocation-free) ----------------
__device__ float g_h[TOKENS * DMODEL];
__device__ __half g_d16[TOKENS * DMODEL];    // fp16 GEMM delta
__device__ __half g_d16b[TOKENS * DMODEL];   // second delta (W2 split-K)
__device__ __half g_a16[TOKENS * DMODEL];
__device__ __half g_s16[TOKENS * DMODEL];
__device__ __half g_ff16[TOKENS * DFF_];     // ff fp16; also qkv fp16
__device__ __half g_ff2[TOKENS * DFF_];      // cq fp16 + ckv fp16
__device__ __half g_w16[16777216];

#define OFF_QKV 0
#define OFF_O   3145728
#define OFF_CQ  4194304
#define OFF_CKV 5242880
#define OFF_CO  7340032
#define OFF_W1  8388608
#define OFF_W2  12582912

// ---------------- helpers ----------------
__device__ __forceinline__ uint32_t smem_u32(const void* p) {
    uint32_t a;
    asm("{ .reg .u64 t; cvta.to.shared.u64 t, %1; cvt.u32.u64 %0, t; }" : "=r"(a) : "l"(p));
    return a;
}
__device__ __forceinline__ void cpa16(uint32_t d, const void* g) {
    asm volatile("cp.async.cg.shared.global [%0], [%1], 16;" :: "r"(d), "l"(g));
}
#define CP_COMMIT() asm volatile("cp.async.commit_group;" ::: "memory")
#define LDSM4(r, a) \
    asm volatile("ldmatrix.sync.aligned.m8n8.x4.shared.b16 {%0,%1,%2,%3}, [%4];" \
        : "=r"((r)[0]), "=r"((r)[1]), "=r"((r)[2]), "=r"((r)[3]) : "r"(a))
#define LDSM4T(r, a) \
    asm volatile("ldmatrix.sync.aligned.m8n8.x4.trans.shared.b16 {%0,%1,%2,%3}, [%4];" \
        : "=r"((r)[0]), "=r"((r)[1]), "=r"((r)[2]), "=r"((r)[3]) : "r"(a))

__device__ __forceinline__ void mma_f16(float* d, const uint32_t* a, const uint32_t* b) {
    asm volatile("mma.sync.aligned.m16n8k16.row.col.f32.f16.f16.f32 "
                 "{%0,%1,%2,%3}, {%4,%5,%6,%7}, {%8,%9}, {%0,%1,%2,%3};"
                 : "+f"(d[0]), "+f"(d[1]), "+f"(d[2]), "+f"(d[3])
                 : "r"(a[0]), "r"(a[1]), "r"(a[2]), "r"(a[3]), "r"(b[0]), "r"(b[1]));
}
__device__ __forceinline__ void mma_h16(uint32_t* d, const uint32_t* a, const uint32_t* b) {
    asm volatile("mma.sync.aligned.m16n8k16.row.col.f16.f16.f16.f16 "
                 "{%0,%1}, {%2,%3,%4,%5}, {%6,%7}, {%0,%1};"
                 : "+r"(d[0]), "+r"(d[1])
                 : "r"(a[0]), "r"(a[1]), "r"(a[2]), "r"(a[3]), "r"(b[0]), "r"(b[1]));
}
__device__ __forceinline__ uint32_t packh2(float a, float b) {
    __half2 t = __float22half2_rn(make_float2(a, b));
    return *(uint32_t*)&t;
}

// ---------------- fp16 single-pass HMMA GEMM (generic strides) -------------
// OUTMODE: 0 = f32 out; 1 = GELU + fp16 out; 2 = fp16 out (qcols scaled 1/8); 3 = fp16 out
template <int ACT, int OUTMODE, int NS, int BN, int ACC16>
__global__ __launch_bounds__(256) void gemm_mma(
    const __half* __restrict__ A, const __half* __restrict__ B,
    const float* __restrict__ bias, float* __restrict__ C,
    __half* __restrict__ Ch, int M, int N, int K, int lda, int ldb, int qcols)
{
    constexpr int WNB = (BN == 256) ? 64 : 32;
    constexpr int NH  = WNB / 16;
    constexpr int B_BYTES = BN * 128;
    constexpr int STG = 16384 + B_BYTES;

    extern __shared__ char smem[];
    uint32_t sb = smem_u32(smem);
    int tid = threadIdx.x, lane = tid & 31, wid = tid >> 5;
    int wm = wid & 1, wn = wid >> 1;
    int bm = blockIdx.y * 128, bn = blockIdx.x * BN;

    float acc[ACC16 ? 1 : 4][2 * NH][4];
    uint32_t acc16[ACC16 ? 4 : 1][2 * NH][2];
    if (ACC16) {
#pragma unroll
        for (int a = 0; a < 4; a++)
#pragma unroll
            for (int b = 0; b < 2 * NH; b++) { acc16[a][b][0] = 0u; acc16[a][b][1] = 0u; }
    } else {
#pragma unroll
        for (int a = 0; a < 4; a++)
#pragma unroll
            for (int b = 0; b < 2 * NH; b++)
#pragma unroll
                for (int c = 0; c < 4; c++) acc[a][b][c] = 0.f;
    }

    auto load_stage = [&](int kc, int s) {
        uint32_t base = sb + s * STG;
#pragma unroll
        for (int i = 0; i < 4; i++) {
            int idx = tid + i * 256;
            int row = idx >> 3, ch = idx & 7;
            cpa16(base + row * 128 + ((ch ^ (row & 7)) << 4),
                  A + (size_t)(bm + row) * lda + kc * 64 + ch * 8);
        }
#pragma unroll
        for (int i = 0; i < BN / 32; i++) {
            int idx = tid + i * 256;
            int row = idx >> 3, ch = idx & 7;
            cpa16(base + 16384 + row * 128 + ((ch ^ (row & 7)) << 4),
                  B + (size_t)(bn + row) * ldb + kc * 64 + ch * 8);
        }
        CP_COMMIT();
    };

    const int NC = K >> 6;
#pragma unroll
    for (int s = 0; s < NS - 1; s++) load_stage(s, s);

    for (int c = 0; c < NC; c++) {
        if (c + NS - 1 < NC) {
            load_stage(c + NS - 1, (c + NS - 1) % NS);
            asm volatile("cp.async.wait_group %0;" :: "n"(NS - 1) : "memory");
        } else {
            asm volatile("cp.async.wait_group 0;" ::: "memory");
        }
        __syncthreads();

        uint32_t aBase = sb + (c % NS) * STG;
#pragma unroll
        for (int ks = 0; ks < 4; ks++) {
            uint32_t ah[4][4];
#pragma unroll
            for (int mt = 0; mt < 4; mt++) {
                int row = wm * 64 + mt * 16 + (lane & 15);
                int ch = ks * 2 + (lane >> 4);
                LDSM4(ah[mt], aBase + row * 128 + ((ch ^ (row & 7)) << 4));
            }
#pragma unroll
            for (int hh = 0; hh < NH / 2; hh++) {
                uint32_t bh[2][4];
#pragma unroll
                for (int j = 0; j < 2; j++) {
                    int nh = hh * 2 + j;
                    int row = wn * WNB + nh * 16 + (lane & 7) + ((lane >> 4) << 3);
                    int ch = ks * 2 + ((lane >> 3) & 1);
                    LDSM4(bh[j], aBase + 16384 + row * 128 + ((ch ^ (row & 7)) << 4));
                }
#pragma unroll
                for (int mt = 0; mt < 4; mt++) {
#pragma unroll
                    for (int ntl = 0; ntl < 4; ntl++) {
                        if (ACC16)
                            mma_h16(acc16[mt][hh * 4 + ntl], ah[mt],
                                    &bh[ntl >> 1][(ntl & 1) * 2]);
                        else
                            mma_f16(acc[mt][hh * 4 + ntl], ah[mt],
                                    &bh[ntl >> 1][(ntl & 1) * 2]);
                    }
                }
            }
        }
        __syncthreads();
    }

#pragma unroll
    for (int mt = 0; mt < 4; mt++) {
#pragma unroll
        for (int nt = 0; nt < 2 * NH; nt++) {
            int col = bn + wn * WNB + nt * 8 + (lane & 3) * 2;
            int r0 = bm + wm * 64 + mt * 16 + (lane >> 2);
            float bb0 = bias ? __ldg(&bias[col]) : 0.f;
            float bb1 = bias ? __ldg(&bias[col + 1]) : 0.f;
            float scl = (OUTMODE == 2 && col < qcols) ? 0.125f : 1.f;
#pragma unroll
            for (int half = 0; half < 2; half++) {
                int r = r0 + half * 8;
                float x0, x1;
                if (ACC16) {
                    float2 v = __half22float2(*(__half2*)&acc16[mt][nt][half]);
                    x0 = v.x + bb0; x1 = v.y + bb1;
                } else {
                    x0 = acc[mt][nt][half * 2 + 0] + bb0;
                    x1 = acc[mt][nt][half * 2 + 1] + bb1;
                }
                if (ACT == 1) {
                    x0 = 0.5f * x0 * (1.f + erff(x0 * 0.70710678118654752f));
                    x1 = 0.5f * x1 * (1.f + erff(x1 * 0.70710678118654752f));
                }
                if (OUTMODE == 2) { x0 *= scl; x1 *= scl; }
                if (OUTMODE == 0) {
                    *(float2*)&C[(size_t)r * N + col] = make_float2(x0, x1);
                } else {
                    *(__half2*)&Ch[(size_t)r * N + col] =
                        __float22half2_rn(make_float2(x0, x1));
                }
            }
        }
    }
}

// ---------------- fp16 flash attention: static grid, 64-query blocks -------
#define ATT_SQ   0
#define ATT_SK   8192
#define ATT_SV   24576
#define ATT_RPB  40960
#define ATT_SMEM 45568

template <int BIAS>
__global__ __launch_bounds__(128) void attn_tc(
    const __half* __restrict__ Qb, int qs,
    const __half* __restrict__ KVb, int kvs, int koff, int voff,
    const float* __restrict__ rpb, __half* __restrict__ Oh)
{
    extern __shared__ char smem[];
    uint32_t sb = smem_u32(smem);
    float* srpb = (float*)(smem + ATT_RPB);
    int tid = threadIdx.x, lane = tid & 31, w = tid >> 5;
    int bq = blockIdx.x, head = blockIdx.y, b = blockIdx.z;

    if (BIAS) {
        for (int i = tid; i < 1087; i += 128)
            srpb[i] = __ldg(&rpb[bq * 64 + i]);
    }

    {
        const __half* qsrc = Qb + (size_t)(b * SEQ + bq * 64) * qs + head * HDIM;
#pragma unroll
        for (int i = 0; i < 4; i++) {
            int idx = tid + i * 128;
            int row = idx >> 3, ch = idx & 7;
            cpa16(sb + ATT_SQ + row * 128 + ((ch ^ (row & 7)) << 4),
                  qsrc + (size_t)row * qs + ch * 8);
        }
    }
    auto load_kv = [&](int t, int s) {
        const __half* kb = KVb + (size_t)(b * SEQ + t * 64) * kvs + koff + head * HDIM;
        const __half* vb = KVb + (size_t)(b * SEQ + t * 64) * kvs + voff + head * HDIM;
#pragma unroll
        for (int i = 0; i < 4; i++) {
            int idx = tid + i * 128;
            int row = idx >> 3, ch = idx & 7;
            uint32_t so = row * 128 + ((ch ^ (row & 7)) << 4) + s * 8192;
            cpa16(sb + ATT_SK + so, kb + (size_t)row * kvs + ch * 8);
            cpa16(sb + ATT_SV + so, vb + (size_t)row * kvs + ch * 8);
        }
        CP_COMMIT();
    };
    load_kv(0, 0);

    uint32_t qf[4][4];
    uint32_t O16[8][2];
#pragma unroll
    for (int j = 0; j < 8; j++) { O16[j][0] = 0u; O16[j][1] = 0u; }
    float l0 = 0.f, l1 = 0.f;

    const int qo_lo = w * 16 + (lane >> 2);

    for (int t = 0; t < 16; t++) {
        __syncthreads();
        if (t + 1 < 16) {
            load_kv(t + 1, (t + 1) & 1);
            asm volatile("cp.async.wait_group 1;" ::: "memory");
        } else {
            asm volatile("cp.async.wait_group 0;" ::: "memory");
        }
        __syncthreads();

        if (t == 0) {
#pragma unroll
            for (int ks = 0; ks < 4; ks++) {
                int row = w * 16 + (lane & 15);
                int ch = ks * 2 + (lane >> 4);
                LDSM4(qf[ks], sb + ATT_SQ + row * 128 + ((ch ^ (row & 7)) << 4));
            }
        }

        uint32_t kbase = sb + ATT_SK + (t & 1) * 8192;
        uint32_t vbase = sb + ATT_SV + (t & 1) * 8192;

        uint32_t sc16[8][2];
#pragma unroll
        for (int j = 0; j < 8; j++) { sc16[j][0] = 0u; sc16[j][1] = 0u; }
#pragma unroll
        for (int p = 0; p < 4; p++) {
#pragma unroll
            for (int ks = 0; ks < 4; ks++) {
                uint32_t kf[4];
                int row = p * 16 + (lane & 7) + ((lane >> 4) << 3);
                int ch = ks * 2 + ((lane >> 3) & 1);
                LDSM4(kf, kbase + row * 128 + ((ch ^ (row & 7)) << 4));
                mma_h16(sc16[2 * p], qf[ks], kf);
                mma_h16(sc16[2 * p + 1], qf[ks], kf + 2);
            }
        }

        float sc[8][4];
        float ps0 = 0.f, ps1 = 0.f;
#pragma unroll
        for (int j = 0; j < 8; j++) {
            float2 vlo = __half22float2(*(__half2*)&sc16[j][0]);
            float2 vhi = __half22float2(*(__half2*)&sc16[j][1]);
            float v4[4] = {vlo.x, vlo.y, vhi.x, vhi.y};
            int keyb = t * 64 + 8 * j + 2 * (lane & 3);
#pragma unroll
            for (int e = 0; e < 4; e++) {
                float s = v4[e];
                if (BIAS) {
                    int qo = qo_lo + (e >> 1) * 8;
                    s += srpb[qo - (keyb + (e & 1)) + 1023];
                }
                float p = __expf(s);
                sc[j][e] = p;
                if ((e >> 1) == 0) ps0 += p; else ps1 += p;
            }
        }
        l0 += ps0; l1 += ps1;

#pragma unroll
        for (int ks = 0; ks < 4; ks++) {
            uint32_t a[4];
            a[0] = packh2(sc[2 * ks][0], sc[2 * ks][1]);
            a[1] = packh2(sc[2 * ks][2], sc[2 * ks][3]);
            a[2] = packh2(sc[2 * ks + 1][0], sc[2 * ks + 1][1]);
            a[3] = packh2(sc[2 * ks + 1][2], sc[2 * ks + 1][3]);
#pragma unroll
            for (int nc = 0; nc < 4; nc++) {
                uint32_t vf[4];
                int row = ks * 16 + (lane & 15);
                int ch = nc * 2 + (lane >> 4);
                LDSM4T(vf, vbase + row * 128 + ((ch ^ (row & 7)) << 4));
                mma_h16(O16[2 * nc], a, vf);
                mma_h16(O16[2 * nc + 1], a, vf + 2);
            }
        }
    }

    l0 += __shfl_xor_sync(0xffffffffu, l0, 1);
    l0 += __shfl_xor_sync(0xffffffffu, l0, 2);
    l1 += __shfl_xor_sync(0xffffffffu, l1, 1);
    l1 += __shfl_xor_sync(0xffffffffu, l1, 2);
    float i0 = 1.f / l0, i1 = 1.f / l1;

    int tok_lo = b * SEQ + bq * 64 + qo_lo;
    size_t base_lo = (size_t)tok_lo * DMODEL + head * HDIM + 2 * (lane & 3);
    size_t base_hi = base_lo + 8 * DMODEL;
#pragma unroll
    for (int j = 0; j < 8; j++) {
        float2 vlo = __half22float2(*(__half2*)&O16[j][0]);
        float2 vhi = __half22float2(*(__half2*)&O16[j][1]);
        *(__half2*)&Oh[base_lo + 8 * j] =
            __float22half2_rn(make_float2(vlo.x * i0, vlo.y * i0));
        *(__half2*)&Oh[base_hi + 8 * j] =
            __float22half2_rn(make_float2(vhi.x * i1, vhi.y * i1));
    }
}

// ---------------- weight convert+transpose: W[K][N] -> fp16 [N][K] ----------
__global__ __launch_bounds__(256) void wconv_t(
    const float* __restrict__ W, __half* __restrict__ out, int K, int N)
{
    __shared__ float s[32][33];
    int tx = threadIdx.x & 31, ty = threadIdx.x >> 5;
    int n0 = blockIdx.x * 32, k0 = blockIdx.y * 32;
#pragma unroll
    for (int i = 0; i < 4; i++)
        s[ty + 8 * i][tx] = W[(size_t)(k0 + ty + 8 * i) * N + n0 + tx];
    __syncthreads();
#pragma unroll
    for (int i = 0; i < 4; i++) {
        int n = ty + 8 * i;
        out[(size_t)(n0 + n) * K + k0 + tx] = __float2half_rn(s[tx][n]);
    }
}

// ---------------- activation convert f32 -> fp16 ----------------
__global__ void conv_act(const float* __restrict__ in, __half* __restrict__ out)
{
    int idx = blockIdx.x * 256 + threadIdx.x;
    float4 v = ((const float4*)in)[idx];
    ((__half2*)out)[idx * 2]     = __float22half2_rn(make_float2(v.x, v.y));
    ((__half2*)out)[idx * 2 + 1] = __float22half2_rn(make_float2(v.z, v.w));
}

// ---------------- step-embed add (+fp16) ----------------
__global__ void add_step_kernel(const float* __restrict__ hidden,
                                const float* __restrict__ se,
                                const int* __restrict__ ts,
                                float* __restrict__ out,
                                __half* __restrict__ o16)
{
    int idx = blockIdx.x * 256 + threadIdx.x;
    int c = ts[0];
    if (c > 19) c = 19;
    float4 h = ((const float4*)hidden)[idx];
    float4 s = ((const float4*)(se + c * DMODEL))[idx & 255];
    float4 o = make_float4(h.x + s.x, h.y + s.y, h.z + s.z, h.w + s.w);
    ((float4*)out)[idx] = o;
    ((__half2*)o16)[idx * 2]     = __float22half2_rn(make_float2(o.x, o.y));
    ((__half2*)o16)[idx * 2 + 1] = __float22half2_rn(make_float2(o.z, o.w));
}

// ---------------- residual + LayerNorm (one or two fp16 deltas) -------------
__global__ __launch_bounds__(256) void ln_kernel(
    const float* __restrict__ A, const __half* __restrict__ BxH,
    const __half* __restrict__ BxH2,
    const float* __restrict__ g, const float* __restrict__ beta,
    float* __restrict__ out, __half* __restrict__ o16)
{
    int row = blockIdx.x, tid = threadIdx.x;
    const float4 va = ((const float4*)(A + (size_t)row * DMODEL))[tid];
    __half2 ha = ((const __half2*)BxH)[(size_t)row * 512 + tid * 2];
    __half2 hb = ((const __half2*)BxH)[(size_t)row * 512 + tid * 2 + 1];
    float2 fa = __half22float2(ha), fb = __half22float2(hb);
    float x0 = va.x + fa.x, x1 = va.y + fa.y, x2 = va.z + fb.x, x3 = va.w + fb.y;
    if (BxH2) {
        __half2 h2a = ((const __half2*)BxH2)[(size_t)row * 512 + tid * 2];
        __half2 h2b = ((const __half2*)BxH2)[(size_t)row * 512 + tid * 2 + 1];
        float2 f2a = __half22float2(h2a), f2b = __half22float2(h2b);
        x0 += f2a.x; x1 += f2a.y; x2 += f2b.x; x3 += f2b.y;
    }

    float s = x0 + x1 + x2 + x3;
    float ss = x0 * x0 + x1 * x1 + x2 * x2 + x3 * x3;
#pragma unroll
    for (int o = 16; o > 0; o >>= 1) {
        s  += __shfl_xor_sync(0xffffffffu, s, o);
        ss += __shfl_xor_sync(0xffffffffu, ss, o);
    }
    __shared__ float sb[16];
    int warp = tid >> 5, lane = tid & 31;
    if (lane == 0) { sb[warp] = s; sb[8 + warp] = ss; }
    __syncthreads();
    if (warp == 0) {
        float s2  = (lane < 8) ? sb[lane] : 0.f;
        float ss2 = (lane < 8) ? sb[8 + lane] : 0.f;
#pragma unroll
        for (int o = 4; o > 0; o >>= 1) {
            s2  += __shfl_xor_sync(0xffffffffu, s2, o);
            ss2 += __shfl_xor_sync(0xffffffffu, ss2, o);
        }
        if (lane == 0) { sb[0] = s2; sb[8] = ss2; }
    }
    __syncthreads();
    float mu  = sb[0] * (1.f / 1024.f);
    float var = sb[8] * (1.f / 1024.f) - mu * mu;
    float rstd = rsqrtf(var + 1e-5f);

    float4 go = ((const float4*)g)[tid];
    float4 bo = ((const float4*)beta)[tid];
    float4 r4;
    r4.x = (x0 - mu) * rstd * go.x + bo.x;
    r4.y = (x1 - mu) * rstd * go.y + bo.y;
    r4.z = (x2 - mu) * rstd * go.z + bo.z;
    r4.w = (x3 - mu) * rstd * go.w + bo.w;
    ((float4*)(out + (size_t)row * DMODEL))[tid] = r4;

    if (o16) {
        size_t base = (size_t)row * DMODEL / 2 + tid * 2;
        ((__half2*)o16)[base]     = __float22half2_rn(make_float2(r4.x, r4.y));
        ((__half2*)o16)[base + 1] = __float22half2_rn(make_float2(r4.z, r4.w));
    }
}

// ---------------- orchestration ----------------
extern "C" void kernel_launch(void* const* d_in, const int* in_sizes, int n_in,
                              void* d_out, int out_size)
{
    const float* hidden = (const float*)d_in[0];
    const float* source = (const float*)d_in[1];
    const int*   tstep  = (const int*)d_in[2];
    const float* sembed = (const float*)d_in[3];
    const float* rpb    = (const float*)d_in[4];
    const float* Wqkv = (const float*)d_in[5],  *bqkv = (const float*)d_in[6];
    const float* Wo   = (const float*)d_in[7],  *bo   = (const float*)d_in[8];
    const float* Wcq  = (const float*)d_in[9],  *bcq  = (const float*)d_in[10];
    const float* Wckv = (const float*)d_in[11], *bckv = (const float*)d_in[12];
    const float* Wco  = (const float*)d_in[13], *bco  = (const float*)d_in[14];
    const float* W1   = (const float*)d_in[15], *b1   = (const float*)d_in[16];
    const float* W2   = (const float*)d_in[17], *b2   = (const float*)d_in[18];
    const float* gs = (const float*)d_in[19], *bts = (const float*)d_in[20];
    const float* gc = (const float*)d_in[21], *btc = (const float*)d_in[22];
    const float* gf = (const float*)d_in[23], *btf = (const float*)d_in[24];
    float* out = (float*)d_out;

    float* ph;
    __half *pd16, *pd16b, *pa16, *ps16, *pff16, *pff2, *pw16;
    cudaGetSymbolAddress((void**)&ph,    g_h);
    cudaGetSymbolAddress((void**)&pd16,  g_d16);
    cudaGetSymbolAddress((void**)&pd16b, g_d16b);
    cudaGetSymbolAddress((void**)&pa16,  g_a16);
    cudaGetSymbolAddress((void**)&ps16,  g_s16);
    cudaGetSymbolAddress((void**)&pff16, g_ff16);
    cudaGetSymbolAddress((void**)&pff2,  g_ff2);
    cudaGetSymbolAddress((void**)&pw16,  g_w16);

    __half* pqkv16 = pff16;
    __half* pcq16  = pff2;
    __half* pckv16 = pff2 + 4194304;

    const int SM_128 = 3 * 32768;
    const int SM_256 = 2 * 49152;
    cudaFuncSetAttribute(gemm_mma<0,2,2,256,1>, cudaFuncAttributeMaxDynamicSharedMemorySize, SM_256);
    cudaFuncSetAttribute(gemm_mma<0,2,3,128,1>, cudaFuncAttributeMaxDynamicSharedMemorySize, SM_128);
    cudaFuncSetAttribute(gemm_mma<0,3,3,128,0>, cudaFuncAttributeMaxDynamicSharedMemorySize, SM_128);
    cudaFuncSetAttribute(gemm_mma<1,2,2,256,0>, cudaFuncAttributeMaxDynamicSharedMemorySize, SM_256);
    cudaFuncSetAttribute(attn_tc<0>, cudaFuncAttributeMaxDynamicSharedMemorySize, ATT_SMEM);
    cudaFuncSetAttribute(attn_tc<1>, cudaFuncAttributeMaxDynamicSharedMemorySize, ATT_SMEM);

    static cudaStream_t s2 = nullptr;
    static cudaEvent_t evFork = nullptr, evQ = nullptr, evW = nullptr,
                       evJoin = nullptr, evL2 = nullptr, evF = nullptr;
    if (!s2) {
        cudaStreamCreateWithFlags(&s2, cudaStreamNonBlocking);
        cudaEventCreateWithFlags(&evFork, cudaEventDisableTiming);
        cudaEventCreateWithFlags(&evQ,    cudaEventDisableTiming);
        cudaEventCreateWithFlags(&evW,    cudaEventDisableTiming);
        cudaEventCreateWithFlags(&evJoin, cudaEventDisableTiming);
        cudaEventCreateWithFlags(&evL2,   cudaEventDisableTiming);
        cudaEventCreateWithFlags(&evF,    cudaEventDisableTiming);
    }

    // ---- fork: s2 converts weights while main does add_step ----
    cudaEventRecord(evFork, 0);
    cudaStreamWaitEvent(s2, evFork, 0);

    add_step_kernel<<<TOKENS * DMODEL / 1024, 256>>>(hidden, sembed, tstep, ph, pa16);

    wconv_t<<<dim3(3072/32, 1024/32), 256, 0, s2>>>(Wqkv, pw16 + OFF_QKV, 1024, 3072);
    cudaEventRecord(evQ, s2);
    wconv_t<<<dim3(1024/32, 1024/32), 256, 0, s2>>>(Wo,   pw16 + OFF_O,   1024, 1024);
    wconv_t<<<dim3(1024/32, 1024/32), 256, 0, s2>>>(Wcq,  pw16 + OFF_CQ,  1024, 1024);
    wconv_t<<<dim3(2048/32, 1024/32), 256, 0, s2>>>(Wckv, pw16 + OFF_CKV, 1024, 2048);
    wconv_t<<<dim3(1024/32, 1024/32), 256, 0, s2>>>(Wco,  pw16 + OFF_CO,  1024, 1024);
    wconv_t<<<dim3(4096/32, 1024/32), 256, 0, s2>>>(W1,   pw16 + OFF_W1,  1024, 4096);
    wconv_t<<<dim3(1024/32, 4096/32), 256, 0, s2>>>(W2,   pw16 + OFF_W2,  4096, 1024);
    cudaEventRecord(evW, s2);
    conv_act<<<TOKENS * DMODEL / 1024, 256, 0, s2>>>(source, ps16);
    gemm_mma<0,2,2,256,1><<<dim3(2048/256, TOKENS/128), 256, SM_256, s2>>>(
        ps16, pw16 + OFF_CKV, bckv, nullptr, pckv16, TOKENS, 2048, 1024, 1024, 1024, 0);
    cudaEventRecord(evJoin, s2);

    // ---- main: QKV (q cols pre-scaled 1/8) -> self-attn ----
    cudaStreamWaitEvent(0, evQ, 0);
    gemm_mma<0,2,3,128,1><<<dim3(3072/128, TOKENS/128), 256, SM_128>>>(
        pa16, pw16 + OFF_QKV, bqkv, nullptr, pqkv16, TOKENS, 3072, 1024, 1024, 1024, 1024);

    dim3 ga(SEQ / 64, NHEAD, 4);
    attn_tc<1><<<ga, 128, ATT_SMEM>>>(pqkv16, 3072, pqkv16, 3072, 1024, 2048, rpb, pa16);

    cudaStreamWaitEvent(0, evW, 0);
    gemm_mma<0,3,3,128,0><<<dim3(1024/128, TOKENS/128), 256, SM_128>>>(
        pa16, pw16 + OFF_O, bo, nullptr, pd16, TOKENS, 1024, 1024, 1024, 1024, 0);
    ln_kernel<<<TOKENS, 256>>>(ph, pd16, nullptr, gs, bts, ph, pa16);

    gemm_mma<0,2,3,128,1><<<dim3(1024/128, TOKENS/128), 256, SM_128>>>(
        pa16, pw16 + OFF_CQ, bcq, nullptr, pcq16, TOKENS, 1024, 1024, 1024, 1024, 1024);

    cudaStreamWaitEvent(0, evJoin, 0);
    attn_tc<0><<<ga, 128, ATT_SMEM>>>(pcq16, 1024, pckv16, 2048, 0, 1024, rpb, pa16);

    gemm_mma<0,3,3,128,0><<<dim3(1024/128, TOKENS/128), 256, SM_128>>>(
        pa16, pw16 + OFF_CO, bco, nullptr, pd16, TOKENS, 1024, 1024, 1024, 1024, 0);
    ln_kernel<<<TOKENS, 256>>>(ph, pd16, nullptr, gc, btc, ph, pa16);
    cudaEventRecord(evL2, 0);

    // ---- FFN pipelined split: W1 N-halves, W2 K-halves ----
    // main: W1a (ff cols 0:2048) then W2a (K 0:2048) -> pd16
    gemm_mma<1,2,2,256,0><<<dim3(2048/256, TOKENS/128), 256, SM_256>>>(
        pa16, pw16 + OFF_W1, b1, nullptr, pff16, TOKENS, 4096, 1024, 1024, 1024, 0);
    // s2: W1b (ff cols 2048:4096) then W2b (K 2048:4096) -> pd16b (no bias)
    cudaStreamWaitEvent(s2, evL2, 0);
    gemm_mma<1,2,2,256,0><<<dim3(2048/256, TOKENS/128), 256, SM_256, s2>>>(
        pa16, pw16 + OFF_W1 + 2048 * 1024, b1 + 2048, nullptr, pff16 + 2048,
        TOKENS, 4096, 1024, 1024, 1024, 0);
    gemm_mma<0,3,3,128,0><<<dim3(1024/128, TOKENS/128), 256, SM_128, s2>>>(
        pff16 + 2048, pw16 + OFF_W2 + 2048, nullptr, nullptr, pd16b,
        TOKENS, 1024, 2048, 4096, 4096, 0);
    cudaEventRecord(evF, s2);

    gemm_mma<0,3,3,128,0><<<dim3(1024/128, TOKENS/128), 256, SM_128>>>(
        pff16, pw16 + OFF_W2, b2, nullptr, pd16, TOKENS, 1024, 2048, 4096, 4096, 0);

    cudaStreamWaitEvent(0, evF, 0);
    ln_kernel<<<TOKENS, 256>>>(ph, pd16, pd16b, gf, btf, out, nullptr);
}